// round 12
// baseline (speedup 1.0000x reference)
#include <cuda_runtime.h>

// Problem constants (mirror the reference's static structure)
#define GD1 32
#define GG  1024          // grid size (32x32)
#define KK  5             // derivative orders
#define BB  4             // batch
#define WD  1.0e-3f       // Pinv weight on derivative rows (1/DS)
#define AL  0.1f          // proximal regularization alpha

// Domain decomposition: each batch's 32 rows split into NCH chunks of RC rows.
// A CTA computes on its chunk + HALO rows each side; with HALO correction
// sweeps after a purely local init, owned rows EXACTLY match the full-grid
// iteration (radius-1 stencil: wrongness advances 1 row per sweep).
#define RC    4           // owned rows per chunk
#define HALO  2           // = number of correction sweeps
#define NCH   8           // chunks per batch (NCH*RC = 32)
#define RMAX  (RC + 2*HALO)   // max local extent rows (8)
#define TPB   (RMAX * 32)     // 256 threads; one warp per local row

// Coord-1 neighbors (i1 +/- 1) live in adjacent LANES of the same warp ->
// exchanged via __shfl_sync (register-resident old iterate, read before update).
// Shared memory only carries the components coord-0 rows need: k in {0,1,3}.
__global__ void __launch_bounds__(TPB, 1)
mg_solve_kernel(const float* __restrict__ coeffs,  // [B,G,K]
                const float* __restrict__ rhs,     // [B,G]
                const float* __restrict__ ivr,     // [B,D1]
                const float* __restrict__ s0,      // [B,D0-1] (batch 0 used for matrix)
                const float* __restrict__ s1,      // [B,D1-1]
                float* __restrict__ out, int out_size)
{
    __shared__ float xs[2][3][TPB];   // double-buffered {x0,x1,x3}, k-major

    const int lr = threadIdx.x >> 5;        // local row 0..RMAX-1 (= warp id)
    const int i1 = threadIdx.x & 31;        // column (= lane id)
    const int c  = blockIdx.x;              // chunk
    const int b  = blockIdx.y;              // batch

    const int own_lo = c * RC;
    const int r_lo = max(0, own_lo - HALO);
    const int r_hi = min(32, own_lo + RC + HALO);
    const int LR   = r_hi - r_lo;           // local extent rows (6..8)

    const int i0r = r_lo + lr;              // real global row (may be >= r_hi: inactive)
    const int i0  = min(i0r, 31);           // clamped for loads
    const int g   = i0 * 32 + i1;           // global node for loads
    const bool owned = (i0r >= own_lo) && (i0r < own_lo + RC);

    const bool f0 = (i0 < 31), k0 = (i0 > 0);
    const bool f1 = (i1 < 31), k1 = (i1 > 0);

    // ---- issue ALL global loads first (overlap DRAM latency with precond math) ----
    const float h0f = f0 ? s0[i0]     : 0.f;
    const float h0b = k0 ? s0[i0 - 1] : 0.f;
    const float h1f = f1 ? s1[i1]     : 0.f;
    const float h1b = k1 ? s1[i1 - 1] : 0.f;
    const float rb  = rhs[b * GG + g];
    const float ivb = ivr[b * GD1 + i1];
    float cb[KK];
    #pragma unroll
    for (int k = 0; k < KK; k++) cb[k] = coeffs[(b * GG + g) * KK + k];
    float c0[KK];                            // batch-0 coefficients (the matrix)
    #pragma unroll
    for (int k = 0; k < KK; k++) c0[k] = coeffs[g * KK + k];

    // h-carrying weights (self-masked through h==0 at edges).
    const float wh0f = WD * h0f, wh0b = WD * h0b;
    const float wh1f = WD * h1f, wh1b = WD * h1b;
    const float dwh0 = wh0f - wh0b, dwh1 = wh1f - wh1b;
    const float whh0 = wh0f * h0f + wh0b * h0b;
    const float whh1 = wh1f * h1f + wh1b * h1b;
    const float ivw = (i0 == 0) ? 1.f : 0.f;
    const float ne0 = (f0 ? 1.f : 0.f) + (k0 ? 1.f : 0.f);
    const float ne1 = (f1 ? 1.f : 0.f) + (k1 ? 1.f : 0.f);

    // Coord-0 neighbor slots in shared (clamped into local extent; clamped reads
    // vanish algebraically or stay confined to halo rows).
    const int lp0 = min(lr + 1, LR - 1) * 32 + i1;
    const int lm0 = max(lr - 1, 0) * 32 + i1;
    const int lme = lr * 32 + i1;           // own slot
    // Coord-1 neighbor lanes (clamped to self; weights self-mask at edges).
    const int lnp = f1 ? i1 + 1 : i1;
    const int lnm = k1 ? i1 - 1 : i1;

    // RHS:  b_v = A^T Pinv A_rhs  (only eq + iv rows carry nonzero A_rhs)
    float bv[KK];
    #pragma unroll
    for (int k = 0; k < KK; k++) bv[k] = cb[k] * rb;
    bv[0] += ivw * ivb;

    // ---- tree part T of the diagonal block: diag t0..t4, edges (0,1)=(1,3)=dwh0, (0,2)=(2,4)=dwh1
    const float t0 = AL + ivw + 2.f * WD * (ne0 + ne1);
    const float t1 = AL + 2.f * WD * ne0 + whh0;
    const float t2 = AL + 2.f * WD * ne1 + whh1;
    const float t3 = AL + whh0;
    const float t4 = AL + whh1;

    // Sparse Cholesky on the tree (eliminate leaves 3,4 then 1,2 into root 0).
    const float i3 = 1.f / t3;            const float l13 = dwh0 * i3;
    const float i4 = 1.f / t4;            const float l24 = dwh1 * i4;
    const float i1f = 1.f / (t1 - dwh0 * l13);  const float l01 = dwh0 * i1f;
    const float i2f = 1.f / (t2 - dwh1 * l24);  const float l02 = dwh1 * i2f;
    const float i0f = 1.f / (t0 - dwh0 * l01 - dwh1 * l02);

#define TSOLVE(y0,y1,y2,y3,y4, r0,r1,r2,r3,r4)                                  \
    { const float f1_ = (r1) - l13 * (r3);                                      \
      const float f2_ = (r2) - l24 * (r4);                                      \
      const float f0_ = (r0) - l01 * f1_ - l02 * f2_;                           \
      y0 = i0f * f0_;                                                           \
      y1 = i1f * f1_ - l01 * y0;                                                \
      y2 = i2f * f2_ - l02 * y0;                                                \
      y3 = i3 * (r3) - l13 * y1;                                                \
      y4 = i4 * (r4) - l24 * y2; }

    // Sherman-Morrison data: q = T^{-1} c0, beta = 1/(1 + c0.q)
    float q0, q1, q2, q3, q4;
    TSOLVE(q0, q1, q2, q3, q4, c0[0], c0[1], c0[2], c0[3], c0[4])
    const float beta = 1.f / (1.f + c0[0]*q0 + c0[1]*q1 + c0[2]*q2 + c0[3]*q3 + c0[4]*q4);

#define PAPPLY(r0,r1,r2,r3,r4)                                                  \
    { float y0_, y1_, y2_, y3_, y4_;                                            \
      TSOLVE(y0_, y1_, y2_, y3_, y4_, r0, r1, r2, r3, r4)                       \
      const float s_ = beta * (c0[0]*y0_ + c0[1]*y1_ + c0[2]*y2_                \
                             + c0[3]*y3_ + c0[4]*y4_);                          \
      xg[0] += y0_ - s_ * q0;  xg[1] += y1_ - s_ * q1;                          \
      xg[2] += y2_ - s_ * q2;  xg[3] += y3_ - s_ * q3;                          \
      xg[4] += y4_ - s_ * q4; }

    // ---- initial iterate: x1 = D^{-1} b (purely local -> exact on all extent rows) ----
    float xg[KK] = {0.f, 0.f, 0.f, 0.f, 0.f};
    PAPPLY(bv[0], bv[1], bv[2], bv[3], bv[4])
    xs[0][0][lme] = xg[0];
    xs[0][1][lme] = xg[1];
    xs[0][2][lme] = xg[3];
    __syncthreads();

    // One block-Jacobi sweep. Coord-0 neighbors from shared buffer RD;
    // coord-1 neighbors via shfl of the CURRENT registers (old iterate:
    // all shuffles execute before xg is updated, warp-uniform control flow).
#define SWEEP(RD, WR, DO_STORE)                                                 \
    {                                                                           \
        /* coord-1 neighbor values via warp shuffle (k = 0,2,4) */              \
        const float p0 = __shfl_sync(0xffffffffu, xg[0], lnp);                  \
        const float p2 = __shfl_sync(0xffffffffu, xg[2], lnp);                  \
        const float p4 = __shfl_sync(0xffffffffu, xg[4], lnp);                  \
        const float m0 = __shfl_sync(0xffffffffu, xg[0], lnm);                  \
        const float m2 = __shfl_sync(0xffffffffu, xg[2], lnm);                  \
        const float m4 = __shfl_sync(0xffffffffu, xg[4], lnm);                  \
        const float dot = c0[0]*xg[0] + c0[1]*xg[1] + c0[2]*xg[2]               \
                        + c0[3]*xg[3] + c0[4]*xg[4];                            \
        float mx[KK];                                                           \
        _Pragma("unroll")                                                       \
        for (int k = 0; k < KK; k++) mx[k] = AL * xg[k] + c0[k] * dot;          \
        mx[0] += ivw * xg[0];                                                   \
        { /* coord 0 rows, pairs (0,1),(1,3): shared reads k={0,1,3} */         \
            const float a0 = xs[RD][0][lp0], a1 = xs[RD][1][lp0],               \
                        a3 = xs[RD][2][lp0];                                    \
            const float b0 = xs[RD][0][lm0], b1 = xs[RD][1][lm0],               \
                        b3 = xs[RD][2][lm0];                                    \
            const float L0 = 2.f*xg[0] - a0 - b0;                               \
            const float L1 = 2.f*xg[1] - a1 - b1;                               \
            mx[0] += 2.f*WD*L0 + dwh0*xg[1] + wh0f*a1 - wh0b*b1;                \
            mx[1] += 2.f*WD*L1 + dwh0*(xg[0] + xg[3]) + whh0*xg[1]              \
                   - wh0f*a0 + wh0b*b0 + wh0f*a3 - wh0b*b3;                     \
            mx[3] += dwh0*xg[1] - wh0f*a1 + wh0b*b1 + whh0*xg[3];               \
        }                                                                       \
        { /* coord 1 rows, pairs (0,2),(2,4): shuffled k={0,2,4} */             \
            const float L0 = 2.f*xg[0] - p0 - m0;                               \
            const float L2 = 2.f*xg[2] - p2 - m2;                               \
            mx[0] += 2.f*WD*L0 + dwh1*xg[2] + wh1f*p2 - wh1b*m2;                \
            mx[2] += 2.f*WD*L2 + dwh1*(xg[0] + xg[4]) + whh1*xg[2]              \
                   - wh1f*p0 + wh1b*m0 + wh1f*p4 - wh1b*m4;                     \
            mx[4] += dwh1*xg[2] - wh1f*p2 + wh1b*m2 + whh1*xg[4];               \
        }                                                                       \
        PAPPLY(bv[0]-mx[0], bv[1]-mx[1], bv[2]-mx[2], bv[3]-mx[3], bv[4]-mx[4]) \
        if (DO_STORE) {                                                         \
            xs[WR][0][lme] = xg[0];                                             \
            xs[WR][1][lme] = xg[1];                                             \
            xs[WR][2][lme] = xg[3];                                             \
            __syncthreads();                                                    \
        }                                                                       \
    }

    // HALO (=2) correction sweeps; owned rows match the full-grid iteration.
    SWEEP(0, 1, true)
    SWEEP(1, 0, false)   // final: nobody reads xs again

#undef SWEEP
#undef PAPPLY
#undef TSOLVE

    // ---- output (owned rows only): reference returns (u0, u); u0 flattens first ----
    if (owned) {
        const int n0 = BB * GG;        // 4096
        const int nu = BB * GG * KK;   // 20480
        if (out_size >= n0 + nu) {
            out[b * GG + g] = xg[0];
            float* u = out + n0;
            #pragma unroll
            for (int k = 0; k < KK; k++) u[(b * GG + g) * KK + k] = xg[k];
        } else if (out_size == nu) {
            #pragma unroll
            for (int k = 0; k < KK; k++) out[(b * GG + g) * KK + k] = xg[k];
        } else {
            out[b * GG + g] = xg[0];
        }
    }
}

extern "C" void kernel_launch(void* const* d_in, const int* in_sizes, int n_in,
                              void* d_out, int out_size)
{
    (void)in_sizes; (void)n_in;
    const float* coeffs = (const float*)d_in[0];  // [4,1,1024,5]
    const float* rhs    = (const float*)d_in[1];  // [4,1,1024]
    const float* ivr    = (const float*)d_in[2];  // [4,1,32]
    const float* s0     = (const float*)d_in[3];  // [4,1,31]
    const float* s1     = (const float*)d_in[4];  // [4,1,31]
    mg_solve_kernel<<<dim3(NCH, BB), TPB>>>(coeffs, rhs, ivr, s0, s1,
                                            (float*)d_out, out_size);
}

// round 13
// speedup vs baseline: 1.1250x; 1.1250x over previous
#include <cuda_runtime.h>

// Problem constants (mirror the reference's static structure)
#define GD1 32
#define GG  1024          // grid size (32x32)
#define KK  5             // derivative orders
#define BB  4             // batch
#define WD  1.0e-3f       // Pinv weight on derivative rows (1/DS)
#define AL  0.1f          // proximal regularization alpha

// Domain decomposition: each batch's 32 rows split into NCH chunks of RC rows.
// A CTA computes on its chunk + HALO rows each side; with HALO correction
// sweeps after a purely local init, owned rows EXACTLY match the full-grid
// iteration (radius-1 stencil: wrongness advances 1 row per sweep).
#define RC    4           // owned rows per chunk
#define HALO  2           // = number of correction sweeps
#define NCH   8           // chunks per batch (NCH*RC = 32)
#define RMAX  (RC + 2*HALO)   // max local extent rows (8)
#define TPB   (RMAX * 32)     // 256 threads; one warp per local row

// Coord-1 neighbors (i1 +/- 1) live in adjacent LANES of the same warp ->
// exchanged via __shfl_sync (register-resident old iterate, read before update).
// Shared memory only carries the components coord-0 rows need: k in {0,1,3}.
__global__ void __launch_bounds__(TPB, 1)
mg_solve_kernel(const float* __restrict__ coeffs,  // [B,G,K]
                const float* __restrict__ rhs,     // [B,G]
                const float* __restrict__ ivr,     // [B,D1]
                const float* __restrict__ s0,      // [B,D0-1] (batch 0 used for matrix)
                const float* __restrict__ s1,      // [B,D1-1]
                float* __restrict__ out, int out_size)
{
    __shared__ float xs[2][3][TPB];   // double-buffered {x0,x1,x3}, k-major

    const int lr = threadIdx.x >> 5;        // local row 0..RMAX-1 (= warp id)
    const int i1 = threadIdx.x & 31;        // column (= lane id)
    const int c  = blockIdx.x;              // chunk
    const int b  = blockIdx.y;              // batch

    const int own_lo = c * RC;
    const int r_lo = max(0, own_lo - HALO);
    const int r_hi = min(32, own_lo + RC + HALO);
    const int LR   = r_hi - r_lo;           // local extent rows (6..8)

    const int i0r = r_lo + lr;              // real global row (may be >= r_hi: inactive)
    const int i0  = min(i0r, 31);           // clamped for loads
    const int g   = i0 * 32 + i1;           // global node for loads
    const bool owned = (i0r >= own_lo) && (i0r < own_lo + RC);

    const bool f0 = (i0 < 31), k0 = (i0 > 0);
    const bool f1 = (i1 < 31), k1 = (i1 > 0);

    // ---- issue ALL global loads first (overlap DRAM latency with precond math) ----
    const float h0f = f0 ? s0[i0]     : 0.f;
    const float h0b = k0 ? s0[i0 - 1] : 0.f;
    const float h1f = f1 ? s1[i1]     : 0.f;
    const float h1b = k1 ? s1[i1 - 1] : 0.f;
    const float rb  = rhs[b * GG + g];
    const float ivb = ivr[b * GD1 + i1];
    float cb[KK];
    #pragma unroll
    for (int k = 0; k < KK; k++) cb[k] = coeffs[(b * GG + g) * KK + k];
    float c0[KK];                            // batch-0 coefficients (the matrix)
    #pragma unroll
    for (int k = 0; k < KK; k++) c0[k] = coeffs[g * KK + k];

    // h-carrying weights (self-masked through h==0 at edges).
    const float wh0f = WD * h0f, wh0b = WD * h0b;
    const float wh1f = WD * h1f, wh1b = WD * h1b;
    const float dwh0 = wh0f - wh0b, dwh1 = wh1f - wh1b;
    const float whh0 = wh0f * h0f + wh0b * h0b;
    const float whh1 = wh1f * h1f + wh1b * h1b;
    const float ivw = (i0 == 0) ? 1.f : 0.f;
    const float ne0 = (f0 ? 1.f : 0.f) + (k0 ? 1.f : 0.f);
    const float ne1 = (f1 ? 1.f : 0.f) + (k1 ? 1.f : 0.f);

    // Coord-0 neighbor slots in shared (clamped into local extent; clamped reads
    // vanish algebraically or stay confined to halo rows).
    const int lp0 = min(lr + 1, LR - 1) * 32 + i1;
    const int lm0 = max(lr - 1, 0) * 32 + i1;
    const int lme = lr * 32 + i1;           // own slot
    // Coord-1 neighbor lanes (clamped to self; weights self-mask at edges).
    const int lnp = f1 ? i1 + 1 : i1;
    const int lnm = k1 ? i1 - 1 : i1;

    // RHS:  b_v = A^T Pinv A_rhs  (only eq + iv rows carry nonzero A_rhs)
    float bv[KK];
    #pragma unroll
    for (int k = 0; k < KK; k++) bv[k] = cb[k] * rb;
    bv[0] += ivw * ivb;

    // ---- tree part T of the diagonal block: diag t0..t4, edges (0,1)=(1,3)=dwh0, (0,2)=(2,4)=dwh1
    const float t0 = AL + ivw + 2.f * WD * (ne0 + ne1);
    const float t1 = AL + 2.f * WD * ne0 + whh0;
    const float t2 = AL + 2.f * WD * ne1 + whh1;
    const float t3 = AL + whh0;
    const float t4 = AL + whh1;

    // Sparse Cholesky on the tree (eliminate leaves 3,4 then 1,2 into root 0).
    const float i3 = 1.f / t3;            const float l13 = dwh0 * i3;
    const float i4 = 1.f / t4;            const float l24 = dwh1 * i4;
    const float i1f = 1.f / (t1 - dwh0 * l13);  const float l01 = dwh0 * i1f;
    const float i2f = 1.f / (t2 - dwh1 * l24);  const float l02 = dwh1 * i2f;
    const float i0f = 1.f / (t0 - dwh0 * l01 - dwh1 * l02);

#define TSOLVE(y0,y1,y2,y3,y4, r0,r1,r2,r3,r4)                                  \
    { const float f1_ = (r1) - l13 * (r3);                                      \
      const float f2_ = (r2) - l24 * (r4);                                      \
      const float f0_ = (r0) - l01 * f1_ - l02 * f2_;                           \
      y0 = i0f * f0_;                                                           \
      y1 = i1f * f1_ - l01 * y0;                                                \
      y2 = i2f * f2_ - l02 * y0;                                                \
      y3 = i3 * (r3) - l13 * y1;                                                \
      y4 = i4 * (r4) - l24 * y2; }

    // Sherman-Morrison data: q = T^{-1} c0, beta = 1/(1 + c0.q)
    float q0, q1, q2, q3, q4;
    TSOLVE(q0, q1, q2, q3, q4, c0[0], c0[1], c0[2], c0[3], c0[4])
    const float beta = 1.f / (1.f + c0[0]*q0 + c0[1]*q1 + c0[2]*q2 + c0[3]*q3 + c0[4]*q4);

#define PAPPLY(r0,r1,r2,r3,r4)                                                  \
    { float y0_, y1_, y2_, y3_, y4_;                                            \
      TSOLVE(y0_, y1_, y2_, y3_, y4_, r0, r1, r2, r3, r4)                       \
      const float s_ = beta * (c0[0]*y0_ + c0[1]*y1_ + c0[2]*y2_                \
                             + c0[3]*y3_ + c0[4]*y4_);                          \
      xg[0] += y0_ - s_ * q0;  xg[1] += y1_ - s_ * q1;                          \
      xg[2] += y2_ - s_ * q2;  xg[3] += y3_ - s_ * q3;                          \
      xg[4] += y4_ - s_ * q4; }

    // ---- initial iterate: x1 = D^{-1} b (purely local -> exact on all extent rows) ----
    float xg[KK] = {0.f, 0.f, 0.f, 0.f, 0.f};
    PAPPLY(bv[0], bv[1], bv[2], bv[3], bv[4])
    xs[0][0][lme] = xg[0];
    xs[0][1][lme] = xg[1];
    xs[0][2][lme] = xg[3];
    __syncthreads();

    // One block-Jacobi sweep. Coord-0 neighbors from shared buffer RD;
    // coord-1 neighbors via shfl of the CURRENT registers (old iterate:
    // all shuffles execute before xg is updated, warp-uniform control flow).
#define SWEEP(RD, WR, DO_STORE)                                                 \
    {                                                                           \
        /* coord-1 neighbor values via warp shuffle (k = 0,2,4) */              \
        const float p0 = __shfl_sync(0xffffffffu, xg[0], lnp);                  \
        const float p2 = __shfl_sync(0xffffffffu, xg[2], lnp);                  \
        const float p4 = __shfl_sync(0xffffffffu, xg[4], lnp);                  \
        const float m0 = __shfl_sync(0xffffffffu, xg[0], lnm);                  \
        const float m2 = __shfl_sync(0xffffffffu, xg[2], lnm);                  \
        const float m4 = __shfl_sync(0xffffffffu, xg[4], lnm);                  \
        const float dot = c0[0]*xg[0] + c0[1]*xg[1] + c0[2]*xg[2]               \
                        + c0[3]*xg[3] + c0[4]*xg[4];                            \
        float mx[KK];                                                           \
        _Pragma("unroll")                                                       \
        for (int k = 0; k < KK; k++) mx[k] = AL * xg[k] + c0[k] * dot;          \
        mx[0] += ivw * xg[0];                                                   \
        { /* coord 0 rows, pairs (0,1),(1,3): shared reads k={0,1,3} */         \
            const float a0 = xs[RD][0][lp0], a1 = xs[RD][1][lp0],               \
                        a3 = xs[RD][2][lp0];                                    \
            const float b0 = xs[RD][0][lm0], b1 = xs[RD][1][lm0],               \
                        b3 = xs[RD][2][lm0];                                    \
            const float L0 = 2.f*xg[0] - a0 - b0;                               \
            const float L1 = 2.f*xg[1] - a1 - b1;                               \
            mx[0] += 2.f*WD*L0 + dwh0*xg[1] + wh0f*a1 - wh0b*b1;                \
            mx[1] += 2.f*WD*L1 + dwh0*(xg[0] + xg[3]) + whh0*xg[1]              \
                   - wh0f*a0 + wh0b*b0 + wh0f*a3 - wh0b*b3;                     \
            mx[3] += dwh0*xg[1] - wh0f*a1 + wh0b*b1 + whh0*xg[3];               \
        }                                                                       \
        { /* coord 1 rows, pairs (0,2),(2,4): shuffled k={0,2,4} */             \
            const float L0 = 2.f*xg[0] - p0 - m0;                               \
            const float L2 = 2.f*xg[2] - p2 - m2;                               \
            mx[0] += 2.f*WD*L0 + dwh1*xg[2] + wh1f*p2 - wh1b*m2;                \
            mx[2] += 2.f*WD*L2 + dwh1*(xg[0] + xg[4]) + whh1*xg[2]              \
                   - wh1f*p0 + wh1b*m0 + wh1f*p4 - wh1b*m4;                     \
            mx[4] += dwh1*xg[2] - wh1f*p2 + wh1b*m2 + whh1*xg[4];               \
        }                                                                       \
        PAPPLY(bv[0]-mx[0], bv[1]-mx[1], bv[2]-mx[2], bv[3]-mx[3], bv[4]-mx[4]) \
        if (DO_STORE) {                                                         \
            xs[WR][0][lme] = xg[0];                                             \
            xs[WR][1][lme] = xg[1];                                             \
            xs[WR][2][lme] = xg[3];                                             \
            __syncthreads();                                                    \
        }                                                                       \
    }

    // HALO (=2) correction sweeps; owned rows match the full-grid iteration.
    SWEEP(0, 1, true)
    SWEEP(1, 0, false)   // final: nobody reads xs again

#undef SWEEP
#undef PAPPLY
#undef TSOLVE

    // ---- output (owned rows only): reference returns (u0, u); u0 flattens first ----
    if (owned) {
        const int n0 = BB * GG;        // 4096
        const int nu = BB * GG * KK;   // 20480
        if (out_size >= n0 + nu) {
            out[b * GG + g] = xg[0];
            float* u = out + n0;
            #pragma unroll
            for (int k = 0; k < KK; k++) u[(b * GG + g) * KK + k] = xg[k];
        } else if (out_size == nu) {
            #pragma unroll
            for (int k = 0; k < KK; k++) out[(b * GG + g) * KK + k] = xg[k];
        } else {
            out[b * GG + g] = xg[0];
        }
    }
}

extern "C" void kernel_launch(void* const* d_in, const int* in_sizes, int n_in,
                              void* d_out, int out_size)
{
    (void)in_sizes; (void)n_in;
    const float* coeffs = (const float*)d_in[0];  // [4,1,1024,5]
    const float* rhs    = (const float*)d_in[1];  // [4,1,1024]
    const float* ivr    = (const float*)d_in[2];  // [4,1,32]
    const float* s0     = (const float*)d_in[3];  // [4,1,31]
    const float* s1     = (const float*)d_in[4];  // [4,1,31]
    mg_solve_kernel<<<dim3(NCH, BB), TPB>>>(coeffs, rhs, ivr, s0, s1,
                                            (float*)d_out, out_size);
}